// round 1
// baseline (speedup 1.0000x reference)
#include <cuda_runtime.h>

// Scratch for per-row hinge values (allocation-free rule: __device__ global).
#define MAX_ROWS 8192
__device__ float g_row_hinge[MAX_ROWS];

// One CTA per row: stream 16384 fp32 (64 KB) with float4 loads, reduce,
// hinge, store to scratch.
__global__ void __launch_bounds__(256) row_hinge_kernel(
    const float* __restrict__ B, int cols)
{
    const int row = blockIdx.x;
    const float4* __restrict__ p =
        reinterpret_cast<const float4*>(B + (size_t)row * (size_t)cols);
    const int n4 = cols >> 2;  // 4096 for cols=16384

    float s = 0.0f;
    // Grid-stride within the row; 256 threads -> 16 float4 each at cols=16384.
    // Unroll 4 to front-batch LDG.128s for MLP.
    int i = threadIdx.x;
    #pragma unroll 4
    for (; i < n4; i += blockDim.x) {
        float4 v = p[i];
        s += (v.x + v.y) + (v.z + v.w);
    }

    // Warp reduce
    #pragma unroll
    for (int o = 16; o > 0; o >>= 1)
        s += __shfl_down_sync(0xffffffffu, s, o);

    __shared__ float ws[8];
    if ((threadIdx.x & 31) == 0) ws[threadIdx.x >> 5] = s;
    __syncthreads();

    if (threadIdx.x < 32) {
        float t = (threadIdx.x < (blockDim.x >> 5)) ? ws[threadIdx.x] : 0.0f;
        #pragma unroll
        for (int o = 4; o > 0; o >>= 1)
            t += __shfl_down_sync(0xffffffffu, t, o);
        if (threadIdx.x == 0)
            g_row_hinge[row] = fmaxf(t - 1.0f, 0.0f);
    }
}

// Single-CTA final reduction: mean of 8192 hinges -> d_out[0].
__global__ void __launch_bounds__(256) final_reduce_kernel(
    float* __restrict__ out, int rows)
{
    float s = 0.0f;
    for (int i = threadIdx.x; i < rows; i += blockDim.x)
        s += g_row_hinge[i];

    #pragma unroll
    for (int o = 16; o > 0; o >>= 1)
        s += __shfl_down_sync(0xffffffffu, s, o);

    __shared__ float ws[8];
    if ((threadIdx.x & 31) == 0) ws[threadIdx.x >> 5] = s;
    __syncthreads();

    if (threadIdx.x < 32) {
        float t = (threadIdx.x < (blockDim.x >> 5)) ? ws[threadIdx.x] : 0.0f;
        #pragma unroll
        for (int o = 4; o > 0; o >>= 1)
            t += __shfl_down_sync(0xffffffffu, t, o);
        if (threadIdx.x == 0)
            out[0] = t / (float)rows;
    }
}

extern "C" void kernel_launch(void* const* d_in, const int* in_sizes, int n_in,
                              void* d_out, int out_size)
{
    const float* B = (const float*)d_in[0];
    const int rows = MAX_ROWS;                 // 8192 per problem spec
    const int cols = in_sizes[0] / rows;       // 16384

    row_hinge_kernel<<<rows, 256>>>(B, cols);
    final_reduce_kernel<<<1, 256>>>((float*)d_out, rows);
}

// round 2
// speedup vs baseline: 1.0731x; 1.0731x over previous
#include <cuda_runtime.h>

#define ROWS 8192

// Allocation-free scratch: accumulator + completion counter.
__device__ float    g_acc   = 0.0f;
__device__ unsigned g_count = 0;

// One CTA per row: stream 16384 fp32 (64 KB) with float4 loads, reduce to a
// row sum, hinge, atomically accumulate. Last CTA writes the mean and resets
// state for the next graph replay.
__global__ void __launch_bounds__(256) bloss_fused_kernel(
    const float* __restrict__ B, float* __restrict__ out, int cols)
{
    const int row = blockIdx.x;
    const float4* __restrict__ p =
        reinterpret_cast<const float4*>(B + (size_t)row * (size_t)cols);
    const int n4 = cols >> 2;  // 4096 for cols=16384

    // 4 independent accumulators: decouple FADD dependency chain from load
    // issue so LDG.128s front-batch (high MLP).
    float s0 = 0.0f, s1 = 0.0f, s2 = 0.0f, s3 = 0.0f;
    int i = threadIdx.x;
    for (; i + 3 * (int)blockDim.x < n4; i += 4 * blockDim.x) {
        float4 v0 = p[i];
        float4 v1 = p[i + blockDim.x];
        float4 v2 = p[i + 2 * blockDim.x];
        float4 v3 = p[i + 3 * blockDim.x];
        s0 += (v0.x + v0.y) + (v0.z + v0.w);
        s1 += (v1.x + v1.y) + (v1.z + v1.w);
        s2 += (v2.x + v2.y) + (v2.z + v2.w);
        s3 += (v3.x + v3.y) + (v3.z + v3.w);
    }
    for (; i < n4; i += blockDim.x) {
        float4 v = p[i];
        s0 += (v.x + v.y) + (v.z + v.w);
    }
    float s = (s0 + s1) + (s2 + s3);

    // Warp reduce
    #pragma unroll
    for (int o = 16; o > 0; o >>= 1)
        s += __shfl_down_sync(0xffffffffu, s, o);

    __shared__ float ws[8];
    if ((threadIdx.x & 31) == 0) ws[threadIdx.x >> 5] = s;
    __syncthreads();

    if (threadIdx.x == 0) {
        float t = ws[0];
        #pragma unroll
        for (int w = 1; w < 8; w++) t += ws[w];

        float h = fmaxf(t - 1.0f, 0.0f);
        atomicAdd(&g_acc, h);
        __threadfence();
        unsigned done = atomicAdd(&g_count, 1u);
        if (done == (unsigned)gridDim.x - 1u) {
            // All CTAs' acc-adds are visible (fence before count-add).
            float total = *(volatile float*)&g_acc;
            out[0] = total / (float)gridDim.x;
            // Reset for next graph replay.
            *(volatile float*)&g_acc = 0.0f;
            *(volatile unsigned*)&g_count = 0u;
            __threadfence();
        }
    }
}

extern "C" void kernel_launch(void* const* d_in, const int* in_sizes, int n_in,
                              void* d_out, int out_size)
{
    const float* B = (const float*)d_in[0];
    const int rows = ROWS;                   // 8192 per problem spec
    const int cols = in_sizes[0] / rows;     // 16384

    bloss_fused_kernel<<<rows, 256>>>(B, (float*)d_out, cols);
}

// round 3
// speedup vs baseline: 1.1305x; 1.0535x over previous
#include <cuda_runtime.h>

#define ROWS  8192
#define BLOCK 256

// Allocation-free scratch: accumulator + completion counter.
__device__ float    g_acc   = 0.0f;
__device__ unsigned g_count = 0;

// One CTA per row: stream 16384 fp32 (64 KB) with float4 streaming loads,
// reduce to a row sum, hinge, atomically accumulate. Last CTA writes the
// mean and resets state for the next graph replay.
__global__ void __launch_bounds__(BLOCK) bloss_fused_kernel(
    const float* __restrict__ B, float* __restrict__ out, int cols)
{
    const int row = blockIdx.x;
    const float4* __restrict__ p =
        reinterpret_cast<const float4*>(B + (size_t)row * (size_t)cols);
    const int n4 = cols >> 2;  // 4096 for cols=16384

    float s0 = 0.0f, s1 = 0.0f, s2 = 0.0f, s3 = 0.0f;
    int i = threadIdx.x;
    // BLOCK is constexpr -> the 3 extra loads use immediate offsets off one
    // address register; one bound-check per 4 LDG.128s. n4 (4096) divides
    // evenly by 4*BLOCK (1024) so the tail loop is dead for this shape.
    for (; i + 3 * BLOCK < n4; i += 4 * BLOCK) {
        float4 v0 = __ldcs(p + i);
        float4 v1 = __ldcs(p + i + BLOCK);
        float4 v2 = __ldcs(p + i + 2 * BLOCK);
        float4 v3 = __ldcs(p + i + 3 * BLOCK);
        s0 += (v0.x + v0.y) + (v0.z + v0.w);
        s1 += (v1.x + v1.y) + (v1.z + v1.w);
        s2 += (v2.x + v2.y) + (v2.z + v2.w);
        s3 += (v3.x + v3.y) + (v3.z + v3.w);
    }
    for (; i < n4; i += BLOCK) {
        float4 v = __ldcs(p + i);
        s0 += (v.x + v.y) + (v.z + v.w);
    }
    float s = (s0 + s1) + (s2 + s3);

    // Warp reduce
    #pragma unroll
    for (int o = 16; o > 0; o >>= 1)
        s += __shfl_down_sync(0xffffffffu, s, o);

    __shared__ float ws[BLOCK / 32];
    if ((threadIdx.x & 31) == 0) ws[threadIdx.x >> 5] = s;
    __syncthreads();

    if (threadIdx.x == 0) {
        float t = ws[0];
        #pragma unroll
        for (int w = 1; w < BLOCK / 32; w++) t += ws[w];

        float h = fmaxf(t - 1.0f, 0.0f);
        atomicAdd(&g_acc, h);
        __threadfence();
        unsigned done = atomicAdd(&g_count, 1u);
        if (done == (unsigned)gridDim.x - 1u) {
            // All CTAs' acc-adds are visible (fence before count-add).
            float total = *(volatile float*)&g_acc;
            out[0] = total / (float)gridDim.x;
            // Reset for next graph replay.
            *(volatile float*)&g_acc = 0.0f;
            *(volatile unsigned*)&g_count = 0u;
            __threadfence();
        }
    }
}

extern "C" void kernel_launch(void* const* d_in, const int* in_sizes, int n_in,
                              void* d_out, int out_size)
{
    const float* B = (const float*)d_in[0];
    const int rows = ROWS;                   // 8192 per problem spec
    const int cols = in_sizes[0] / rows;     // 16384

    bloss_fused_kernel<<<rows, BLOCK>>>(B, (float*)d_out, cols);
}